// round 8
// baseline (speedup 1.0000x reference)
#include <cuda_runtime.h>
#include <stdint.h>

#define N_STRUCT   1000
#define ATOMS      100
#define N_SAMP     100000
#define N_GRAD     500000
#define DFEAT      128
#define NSEG       (N_STRUCT * ATOMS)      // 100000
#define ROW_F4     96                      // 3*128/4
#define GRAD_OUT_OFFSET (N_STRUCT * DFEAT)

#define SCAN_TILE  1024
#define SCAN_NB    ((NSEG + SCAN_TILE - 1) / SCAN_TILE)   // 98

#define COUNT_BLOCKS  ((N_GRAD + 255) / 256)   // 1954
#define VALUES_BLOCKS (N_STRUCT / 2)           // 500
#define GATHER_BLOCKS (NSEG / 8)               // 12500 (8 warps/block, 1 seg/warp)

// -------- scratch (device globals; zero-initialized at module load) --------
// Invariants at kernel_launch entry (restored by gather every call):
//   g_count == 0, g_bsum == 0, g_done == 0
__device__ int g_count[NSEG];
__device__ int g_start[NSEG + 1];
__device__ int g_rows[N_GRAD];
__device__ int g_segpos[N_GRAD];   // (seg << 8) | within-segment rank
__device__ int g_bsum[SCAN_NB];    // tile-sum + 1 (0 == not ready)
__device__ int g_done;             // scan-phase completion counter

// ---------------------------------------------------------------------------
// Kernel 1 (fused): degree count — the atomicAdd return value IS the row's
// within-segment rank, stored packed. Overlapped with the values segment-sum.
// ---------------------------------------------------------------------------
__global__ void count_values_kernel(const int*   __restrict__ gstruct,
                                    const int*   __restrict__ gatom,
                                    const float* __restrict__ values,
                                    const int*   __restrict__ sid,
                                    float*       __restrict__ out) {
    if (blockIdx.x < COUNT_BLOCKS) {
        int i = blockIdx.x * 256 + threadIdx.x;
        if (i < N_GRAD) {
            int seg = gstruct[i] * ATOMS + gatom[i];
            int pos = atomicAdd(&g_count[seg], 1);   // rank within segment
            g_segpos[i] = (seg << 8) | pos;          // pos <= ~25 << 256
        }
    } else {
        // values segment-sum: 2 structures per block (sorted ids -> bsearch)
        int vb   = blockIdx.x - COUNT_BLOCKS;
        int half = threadIdx.x >> 7;
        int d    = threadIdx.x & 127;
        int s    = vb * 2 + half;

        __shared__ int s_lo[2], s_hi[2];
        if (d == 0) {
            int lo = 0, hi = N_SAMP;
            while (lo < hi) { int m = (lo + hi) >> 1; if (sid[m] < s) lo = m + 1; else hi = m; }
            s_lo[half] = lo;
            lo = s_lo[half]; hi = N_SAMP;
            while (lo < hi) { int m = (lo + hi) >> 1; if (sid[m] < s + 1) lo = m + 1; else hi = m; }
            s_hi[half] = lo;
        }
        __syncthreads();

        float acc = 0.f;
        int lo = s_lo[half], hi = s_hi[half];
        for (int r = lo; r < hi; ++r)
            acc += values[(long long)r * DFEAT + d];
        __stcs(out + (long long)s * DFEAT + d, acc);
    }
}

// ---------------------------------------------------------------------------
// Kernel 2: scan + atomic-free scatter in ONE launch.
//   Phase A: 98 blocks scan their 1024-seg tile; exclusive block offset via
//            decoupled lookback (g_bsum publish + spin). Writes g_start.
//   grid sync: fence + g_done counter spin (98 blocks all co-resident).
//   Phase B: grid-stride scatter: slot = g_start[seg] + pos. No atomics.
// ---------------------------------------------------------------------------
__global__ void scan_scatter_kernel() {
    __shared__ int sh[SCAN_TILE];
    __shared__ int s_boff;
    int b = blockIdx.x;
    int i = b * SCAN_TILE + threadIdx.x;

    // --- Phase A: tile scan ---
    int v = (i < NSEG) ? g_count[i] : 0;
    sh[threadIdx.x] = v;
    __syncthreads();
    for (int off = 1; off < SCAN_TILE; off <<= 1) {
        int t = (threadIdx.x >= off) ? sh[threadIdx.x - off] : 0;
        __syncthreads();
        sh[threadIdx.x] += t;
        __syncthreads();
    }

    if (threadIdx.x == SCAN_TILE - 1) {
        volatile int* p = g_bsum;
        p[b] = sh[SCAN_TILE - 1] + 1;       // publish tile total (+1 = ready)
    }

    if (threadIdx.x < 32) {                  // lookback over blocks j < b
        int acc = 0;
        volatile int* p = g_bsum;
        for (int j = (int)threadIdx.x; j < b; j += 32) {
            int w;
            while ((w = p[j]) == 0) { }
            acc += w - 1;
        }
        #pragma unroll
        for (int off = 16; off > 0; off >>= 1)
            acc += __shfl_down_sync(0xffffffffu, acc, off);
        if (threadIdx.x == 0) s_boff = acc;
    }
    __syncthreads();

    if (i < NSEG) g_start[i] = sh[threadIdx.x] - v + s_boff;
    if (i == NSEG - 1) g_start[NSEG] = N_GRAD;

    // --- grid sync (98 co-resident blocks) ---
    __syncthreads();
    if (threadIdx.x == 0) {
        __threadfence();
        atomicAdd(&g_done, 1);
    }
    if (threadIdx.x == 0) {
        volatile int* d = &g_done;
        while (*d < SCAN_NB) { }
    }
    __syncthreads();
    __threadfence();

    // --- Phase B: atomic-free scatter, grid-stride (5 rows/thread, MLP) ---
    for (int r = b * SCAN_TILE + threadIdx.x; r < N_GRAD; r += SCAN_NB * SCAN_TILE) {
        int sp  = g_segpos[r];
        int seg = sp >> 8;
        int pos = sp & 255;
        g_rows[g_start[seg] + pos] = r;
    }
}

// ---------------------------------------------------------------------------
// Kernel 3: gather-reduce (proven hot path, 144.9us @ 6.1TB/s). One warp per
// segment; row ids prefetched + shfl broadcast -> all loads address-ready.
// Restores all scratch invariants.
// ---------------------------------------------------------------------------
__global__ void gather_kernel(const float4* __restrict__ grad4,
                              float*        __restrict__ out_grad) {
    int zi = blockIdx.x * 256 + threadIdx.x;
    if (zi < NSEG) g_count[zi] = 0;          // restore invariant
    if (zi < SCAN_NB) g_bsum[zi] = 0;
    if (zi == 0) g_done = 0;

    int warp_id = (blockIdx.x * 256 + threadIdx.x) >> 5;
    int lane    = threadIdx.x & 31;

    int lo  = g_start[warp_id];
    int hi  = g_start[warp_id + 1];
    int cnt = hi - lo;

    int rid = (lane < cnt) ? g_rows[lo + lane] : 0;

    float4 a0 = make_float4(0.f, 0.f, 0.f, 0.f);
    float4 a1 = a0, a2 = a0;

    int n32 = cnt < 32 ? cnt : 32;
    #pragma unroll 4
    for (int p = 0; p < n32; ++p) {
        long long row = __shfl_sync(0xffffffffu, rid, p);
        const float4* src = grad4 + row * ROW_F4;
        float4 v0 = __ldcs(src + lane);
        float4 v1 = __ldcs(src + lane + 32);
        float4 v2 = __ldcs(src + lane + 64);
        a0.x += v0.x; a0.y += v0.y; a0.z += v0.z; a0.w += v0.w;
        a1.x += v1.x; a1.y += v1.y; a1.z += v1.z; a1.w += v1.w;
        a2.x += v2.x; a2.y += v2.y; a2.z += v2.z; a2.w += v2.w;
    }
    for (int p = 32; p < cnt; ++p) {         // overflow fallback (never hit)
        long long row = g_rows[lo + p];
        const float4* src = grad4 + row * ROW_F4;
        float4 v0 = __ldcs(src + lane);
        float4 v1 = __ldcs(src + lane + 32);
        float4 v2 = __ldcs(src + lane + 64);
        a0.x += v0.x; a0.y += v0.y; a0.z += v0.z; a0.w += v0.w;
        a1.x += v1.x; a1.y += v1.y; a1.z += v1.z; a1.w += v1.w;
        a2.x += v2.x; a2.y += v2.y; a2.z += v2.z; a2.w += v2.w;
    }

    float4* dst = (float4*)(out_grad + (long long)warp_id * (3 * DFEAT));
    __stcs(dst + lane,      a0);
    __stcs(dst + lane + 32, a1);
    __stcs(dst + lane + 64, a2);
}

// ---------------------------------------------------------------------------
extern "C" void kernel_launch(void* const* d_in, const int* in_sizes, int n_in,
                              void* d_out, int out_size) {
    const float*  values  = (const float*)d_in[0];
    const int*    sid     = (const int*)  d_in[1];
    const float4* grad4   = (const float4*)d_in[2];
    const int*    gstruct = (const int*)  d_in[3];
    const int*    gatom   = (const int*)  d_in[4];

    float* out      = (float*)d_out;
    float* out_grad = out + GRAD_OUT_OFFSET;

    count_values_kernel<<<COUNT_BLOCKS + VALUES_BLOCKS, 256>>>(
        gstruct, gatom, values, sid, out);
    scan_scatter_kernel<<<SCAN_NB, SCAN_TILE>>>();
    gather_kernel<<<GATHER_BLOCKS, 256>>>(grad4, out_grad);
}

// round 9
// speedup vs baseline: 1.0821x; 1.0821x over previous
#include <cuda_runtime.h>
#include <stdint.h>

#define N_STRUCT   1000
#define ATOMS      100
#define N_SAMP     100000
#define N_GRAD     500000
#define DFEAT      128
#define NSEG       (N_STRUCT * ATOMS)      // 100000
#define ROW_F4     96                      // 3*128/4
#define GRAD_OUT_OFFSET (N_STRUCT * DFEAT)

#define SCAN_TILE  1024
#define SCAN_NB    ((NSEG + SCAN_TILE - 1) / SCAN_TILE)   // 98
#define PREP_THREADS (SCAN_NB * SCAN_TILE)                 // 100352

#define VALUES_NB  ((N_STRUCT + 7) / 8)        // 125 (8 structures / 1024-thr block)
#define PREP_BLOCKS (SCAN_NB + VALUES_NB)      // 223
#define GATHER_BLOCKS (NSEG / 8)               // 12500 (8 warps/block, 1 seg/warp)

// -------- scratch (device globals; zero-initialized at module load) --------
// Invariants at kernel_launch entry (restored by gather every call):
//   g_count == 0, g_bsum == 0, g_sync1 == 0, g_sync2 == 0
__device__ int g_count[NSEG];
__device__ int g_start[NSEG + 1];
__device__ int g_rows[N_GRAD];
__device__ int g_segpos[N_GRAD];   // (seg << 8) | within-segment rank
__device__ int g_bsum[SCAN_NB];    // tile-sum + 1 (0 == not ready)
__device__ int g_sync1, g_sync2;   // grid-sync counters (scan blocks only)

// ---------------------------------------------------------------------------
// Kernel 1 (persistent prep):
//   bid <  SCAN_NB : count -> gridsync -> scan(+lookback) -> gridsync -> scatter
//                    (98 blocks, all placed in wave 1 -> syncs are safe)
//   bid >= SCAN_NB : values segment-sums, 8 structures per 1024-thr block,
//                    4-way unrolled accumulators (MLP), no sync participation.
// ---------------------------------------------------------------------------
__global__ __launch_bounds__(1024) void prep_kernel(
        const int*   __restrict__ gstruct,
        const int*   __restrict__ gatom,
        const float* __restrict__ values,
        const int*   __restrict__ sid,
        float*       __restrict__ out) {
    if (blockIdx.x < SCAN_NB) {
        int tid = threadIdx.x;
        int b   = blockIdx.x;
        int gth = b * SCAN_TILE + tid;

        // --- phase 1: degree count; atomicAdd return value = rank ---
        for (int r = gth; r < N_GRAD; r += PREP_THREADS) {
            int seg = __ldcs(gstruct + r) * ATOMS + __ldcs(gatom + r);
            int pos = atomicAdd(&g_count[seg], 1);
            g_segpos[r] = (seg << 8) | pos;          // pos <= ~25
        }
        __syncthreads();
        if (tid == 0) {
            __threadfence();
            atomicAdd(&g_sync1, 1);
            volatile int* p = &g_sync1;
            while (*p < SCAN_NB) { }
        }
        __syncthreads();

        // --- phase 2: tile scan + decoupled lookback ---
        __shared__ int sh[SCAN_TILE];
        __shared__ int s_boff;
        int i = b * SCAN_TILE + tid;
        int v = (i < NSEG) ? g_count[i] : 0;
        sh[tid] = v;
        __syncthreads();
        for (int off = 1; off < SCAN_TILE; off <<= 1) {
            int t = (tid >= off) ? sh[tid - off] : 0;
            __syncthreads();
            sh[tid] += t;
            __syncthreads();
        }
        if (tid == SCAN_TILE - 1) {
            volatile int* p = g_bsum;
            p[b] = sh[SCAN_TILE - 1] + 1;            // publish (+1 = ready)
        }
        if (tid < 32) {                               // lookback j < b
            int acc = 0;
            volatile int* p = g_bsum;
            for (int j = tid; j < b; j += 32) {
                int w;
                while ((w = p[j]) == 0) { }
                acc += w - 1;
            }
            #pragma unroll
            for (int off = 16; off > 0; off >>= 1)
                acc += __shfl_down_sync(0xffffffffu, acc, off);
            if (tid == 0) s_boff = acc;
        }
        __syncthreads();
        if (i < NSEG) g_start[i] = sh[tid] - v + s_boff;
        if (i == NSEG - 1) g_start[NSEG] = N_GRAD;

        __syncthreads();
        if (tid == 0) {
            __threadfence();
            atomicAdd(&g_sync2, 1);
            volatile int* p = &g_sync2;
            while (*p < SCAN_NB) { }
        }
        __syncthreads();

        // --- phase 3: atomic-free scatter ---
        for (int r = gth; r < N_GRAD; r += PREP_THREADS) {
            int sp  = g_segpos[r];
            int seg = sp >> 8;
            g_rows[g_start[seg] + (sp & 255)] = r;
        }
    } else {
        // --- values segment-sum: 8 structures per block (sorted -> bsearch)
        int vb  = blockIdx.x - SCAN_NB;
        int sub = threadIdx.x >> 7;            // 0..7
        int d   = threadIdx.x & 127;
        int s   = vb * 8 + sub;

        __shared__ int s_lo[8], s_hi[8];
        if (s < N_STRUCT) {
            if (d == 0) {
                int lo = 0, hi = N_SAMP;
                while (lo < hi) { int m = (lo + hi) >> 1; if (sid[m] < s) lo = m + 1; else hi = m; }
                s_lo[sub] = lo;
                lo = s_lo[sub]; hi = N_SAMP;
                while (lo < hi) { int m = (lo + hi) >> 1; if (sid[m] < s + 1) lo = m + 1; else hi = m; }
                s_hi[sub] = lo;
            }
        }
        __syncthreads();
        if (s >= N_STRUCT) return;

        int lo = s_lo[sub], hi = s_hi[sub];
        // 4 independent accumulators -> 4x MLP on the latency-bound loop
        float a0 = 0.f, a1 = 0.f, a2 = 0.f, a3 = 0.f;
        int r = lo;
        for (; r + 3 < hi; r += 4) {
            a0 += __ldcs(values + (long long)(r    ) * DFEAT + d);
            a1 += __ldcs(values + (long long)(r + 1) * DFEAT + d);
            a2 += __ldcs(values + (long long)(r + 2) * DFEAT + d);
            a3 += __ldcs(values + (long long)(r + 3) * DFEAT + d);
        }
        for (; r < hi; ++r)
            a0 += __ldcs(values + (long long)r * DFEAT + d);
        __stcs(out + (long long)s * DFEAT + d, (a0 + a1) + (a2 + a3));
    }
}

// ---------------------------------------------------------------------------
// Kernel 2: gather-reduce (proven: 144.9us @ 6.1TB/s). One warp per segment;
// row ids prefetched into lanes + shfl broadcast -> all loads address-ready.
// Restores all scratch invariants.
// ---------------------------------------------------------------------------
__global__ void gather_kernel(const float4* __restrict__ grad4,
                              float*        __restrict__ out_grad) {
    int zi = blockIdx.x * 256 + threadIdx.x;
    if (zi < NSEG) g_count[zi] = 0;
    if (zi < SCAN_NB) g_bsum[zi] = 0;
    if (zi == 0) { g_sync1 = 0; g_sync2 = 0; }

    int warp_id = (blockIdx.x * 256 + threadIdx.x) >> 5;
    int lane    = threadIdx.x & 31;

    int lo  = g_start[warp_id];
    int hi  = g_start[warp_id + 1];
    int cnt = hi - lo;

    int rid = (lane < cnt) ? g_rows[lo + lane] : 0;

    float4 a0 = make_float4(0.f, 0.f, 0.f, 0.f);
    float4 a1 = a0, a2 = a0;

    int n32 = cnt < 32 ? cnt : 32;
    #pragma unroll 4
    for (int p = 0; p < n32; ++p) {
        long long row = __shfl_sync(0xffffffffu, rid, p);
        const float4* src = grad4 + row * ROW_F4;
        float4 v0 = __ldcs(src + lane);
        float4 v1 = __ldcs(src + lane + 32);
        float4 v2 = __ldcs(src + lane + 64);
        a0.x += v0.x; a0.y += v0.y; a0.z += v0.z; a0.w += v0.w;
        a1.x += v1.x; a1.y += v1.y; a1.z += v1.z; a1.w += v1.w;
        a2.x += v2.x; a2.y += v2.y; a2.z += v2.z; a2.w += v2.w;
    }
    for (int p = 32; p < cnt; ++p) {         // overflow fallback (never hit)
        long long row = g_rows[lo + p];
        const float4* src = grad4 + row * ROW_F4;
        float4 v0 = __ldcs(src + lane);
        float4 v1 = __ldcs(src + lane + 32);
        float4 v2 = __ldcs(src + lane + 64);
        a0.x += v0.x; a0.y += v0.y; a0.z += v0.z; a0.w += v0.w;
        a1.x += v1.x; a1.y += v1.y; a1.z += v1.z; a1.w += v1.w;
        a2.x += v2.x; a2.y += v2.y; a2.z += v2.z; a2.w += v2.w;
    }

    float4* dst = (float4*)(out_grad + (long long)warp_id * (3 * DFEAT));
    __stcs(dst + lane,      a0);
    __stcs(dst + lane + 32, a1);
    __stcs(dst + lane + 64, a2);
}

// ---------------------------------------------------------------------------
extern "C" void kernel_launch(void* const* d_in, const int* in_sizes, int n_in,
                              void* d_out, int out_size) {
    const float*  values  = (const float*)d_in[0];
    const int*    sid     = (const int*)  d_in[1];
    const float4* grad4   = (const float4*)d_in[2];
    const int*    gstruct = (const int*)  d_in[3];
    const int*    gatom   = (const int*)  d_in[4];

    float* out      = (float*)d_out;
    float* out_grad = out + GRAD_OUT_OFFSET;

    prep_kernel<<<PREP_BLOCKS, 1024>>>(gstruct, gatom, values, sid, out);
    gather_kernel<<<GATHER_BLOCKS, 256>>>(grad4, out_grad);
}

// round 10
// speedup vs baseline: 1.0838x; 1.0015x over previous
#include <cuda_runtime.h>
#include <stdint.h>

#define N_STRUCT   1000
#define ATOMS      100
#define N_SAMP     100000
#define N_GRAD     500000
#define DFEAT      128
#define NSEG       (N_STRUCT * ATOMS)      // 100000
#define ROW_F4     96                      // 3*128/4
#define GRAD_OUT_OFFSET (N_STRUCT * DFEAT)

#define SCAN_TILE  1024
#define SCAN_NB    ((NSEG + SCAN_TILE - 1) / SCAN_TILE)   // 98
#define PREP_THREADS (SCAN_NB * SCAN_TILE)                 // 100352

#define VALUES_NB  ((N_STRUCT + 7) / 8)        // 125
#define PREP_BLOCKS (SCAN_NB + VALUES_NB)      // 223

// gather: 3 warps per segment (one per 512B chunk of the 1536B row)
#define GATHER_WARPS  (NSEG * 3)               // 300000
#define GATHER_BLOCKS (GATHER_WARPS / 8)       // 37500

// -------- scratch (device globals; zero-initialized at module load) --------
// Invariants at kernel_launch entry (restored by gather every call):
//   g_count == 0, g_bsum == 0, g_sync1 == 0, g_sync2 == 0
__device__ int g_count[NSEG];
__device__ int g_start[NSEG + 1];
__device__ int g_rows[N_GRAD];
__device__ int g_segpos[N_GRAD];   // (seg << 8) | within-segment rank
__device__ int g_bsum[SCAN_NB];    // tile-sum + 1 (0 == not ready)
__device__ int g_sync1, g_sync2;   // grid-sync counters (scan blocks only)

// ---------------------------------------------------------------------------
// Kernel 1 (persistent prep): count -> gridsync -> scan(+lookback) ->
// gridsync -> atomic-free scatter; values sums in extra non-sync blocks.
// ---------------------------------------------------------------------------
__global__ __launch_bounds__(1024) void prep_kernel(
        const int*   __restrict__ gstruct,
        const int*   __restrict__ gatom,
        const float* __restrict__ values,
        const int*   __restrict__ sid,
        float*       __restrict__ out) {
    if (blockIdx.x < SCAN_NB) {
        int tid = threadIdx.x;
        int b   = blockIdx.x;
        int gth = b * SCAN_TILE + tid;

        // --- phase 1: degree count; atomicAdd return value = rank ---
        for (int r = gth; r < N_GRAD; r += PREP_THREADS) {
            int seg = __ldcs(gstruct + r) * ATOMS + __ldcs(gatom + r);
            int pos = atomicAdd(&g_count[seg], 1);
            g_segpos[r] = (seg << 8) | pos;          // pos <= ~25
        }
        __syncthreads();
        if (tid == 0) {
            __threadfence();
            atomicAdd(&g_sync1, 1);
            volatile int* p = &g_sync1;
            while (*p < SCAN_NB) { }
        }
        __syncthreads();

        // --- phase 2: tile scan + decoupled lookback ---
        __shared__ int sh[SCAN_TILE];
        __shared__ int s_boff;
        int i = b * SCAN_TILE + tid;
        int v = (i < NSEG) ? g_count[i] : 0;
        sh[tid] = v;
        __syncthreads();
        for (int off = 1; off < SCAN_TILE; off <<= 1) {
            int t = (tid >= off) ? sh[tid - off] : 0;
            __syncthreads();
            sh[tid] += t;
            __syncthreads();
        }
        if (tid == SCAN_TILE - 1) {
            volatile int* p = g_bsum;
            p[b] = sh[SCAN_TILE - 1] + 1;            // publish (+1 = ready)
        }
        if (tid < 32) {                               // lookback j < b
            int acc = 0;
            volatile int* p = g_bsum;
            for (int j = tid; j < b; j += 32) {
                int w;
                while ((w = p[j]) == 0) { }
                acc += w - 1;
            }
            #pragma unroll
            for (int off = 16; off > 0; off >>= 1)
                acc += __shfl_down_sync(0xffffffffu, acc, off);
            if (tid == 0) s_boff = acc;
        }
        __syncthreads();
        if (i < NSEG) g_start[i] = sh[tid] - v + s_boff;
        if (i == NSEG - 1) g_start[NSEG] = N_GRAD;

        __syncthreads();
        if (tid == 0) {
            __threadfence();
            atomicAdd(&g_sync2, 1);
            volatile int* p = &g_sync2;
            while (*p < SCAN_NB) { }
        }
        __syncthreads();

        // --- phase 3: atomic-free scatter ---
        for (int r = gth; r < N_GRAD; r += PREP_THREADS) {
            int sp  = g_segpos[r];
            int seg = sp >> 8;
            g_rows[g_start[seg] + (sp & 255)] = r;
        }
    } else {
        // --- values segment-sum: 8 structures per block (sorted -> bsearch)
        int vb  = blockIdx.x - SCAN_NB;
        int sub = threadIdx.x >> 7;            // 0..7
        int d   = threadIdx.x & 127;
        int s   = vb * 8 + sub;

        __shared__ int s_lo[8], s_hi[8];
        if (s < N_STRUCT) {
            if (d == 0) {
                int lo = 0, hi = N_SAMP;
                while (lo < hi) { int m = (lo + hi) >> 1; if (sid[m] < s) lo = m + 1; else hi = m; }
                s_lo[sub] = lo;
                lo = s_lo[sub]; hi = N_SAMP;
                while (lo < hi) { int m = (lo + hi) >> 1; if (sid[m] < s + 1) lo = m + 1; else hi = m; }
                s_hi[sub] = lo;
            }
        }
        __syncthreads();
        if (s >= N_STRUCT) return;

        int lo = s_lo[sub], hi = s_hi[sub];
        float a0 = 0.f, a1 = 0.f, a2 = 0.f, a3 = 0.f;
        int r = lo;
        for (; r + 3 < hi; r += 4) {
            a0 += __ldcs(values + (long long)(r    ) * DFEAT + d);
            a1 += __ldcs(values + (long long)(r + 1) * DFEAT + d);
            a2 += __ldcs(values + (long long)(r + 2) * DFEAT + d);
            a3 += __ldcs(values + (long long)(r + 3) * DFEAT + d);
        }
        for (; r < hi; ++r)
            a0 += __ldcs(values + (long long)r * DFEAT + d);
        __stcs(out + (long long)s * DFEAT + d, (a0 + a1) + (a2 + a3));
    }
}

// ---------------------------------------------------------------------------
// Kernel 2: gather-reduce, THREE warps per segment (one per 512B chunk).
// Low register pressure (1 float4 accumulator) -> high occupancy -> more
// outstanding loads. Index traffic re-read 3x (negligible, +6MB).
// Restores all scratch invariants.
// ---------------------------------------------------------------------------
__global__ __launch_bounds__(256) void gather_kernel(
        const float4* __restrict__ grad4,
        float*        __restrict__ out_grad) {
    int zi = blockIdx.x * 256 + threadIdx.x;
    if (zi < NSEG) g_count[zi] = 0;
    if (zi < SCAN_NB) g_bsum[zi] = 0;
    if (zi == 0) { g_sync1 = 0; g_sync2 = 0; }

    int warp_id = (blockIdx.x * 256 + threadIdx.x) >> 5;
    int lane    = threadIdx.x & 31;

    int seg   = warp_id / 3;
    int chunk = warp_id - seg * 3;          // 0,1,2

    int lo  = g_start[seg];
    int hi  = g_start[seg + 1];
    int cnt = hi - lo;

    int rid = (lane < cnt) ? g_rows[lo + lane] : 0;

    int coff = chunk * 32 + lane;           // float4 offset within the row
    float4 a = make_float4(0.f, 0.f, 0.f, 0.f);

    int n32 = cnt < 32 ? cnt : 32;
    #pragma unroll 4
    for (int p = 0; p < n32; ++p) {
        long long row = __shfl_sync(0xffffffffu, rid, p);
        float4 v = __ldcs(grad4 + row * ROW_F4 + coff);
        a.x += v.x; a.y += v.y; a.z += v.z; a.w += v.w;
    }
    for (int p = 32; p < cnt; ++p) {        // overflow fallback (never hit)
        long long row = g_rows[lo + p];
        float4 v = __ldcs(grad4 + row * ROW_F4 + coff);
        a.x += v.x; a.y += v.y; a.z += v.z; a.w += v.w;
    }

    float4* dst = (float4*)(out_grad + (long long)seg * (3 * DFEAT));
    __stcs(dst + coff, a);
}

// ---------------------------------------------------------------------------
extern "C" void kernel_launch(void* const* d_in, const int* in_sizes, int n_in,
                              void* d_out, int out_size) {
    const float*  values  = (const float*)d_in[0];
    const int*    sid     = (const int*)  d_in[1];
    const float4* grad4   = (const float4*)d_in[2];
    const int*    gstruct = (const int*)  d_in[3];
    const int*    gatom   = (const int*)  d_in[4];

    float* out      = (float*)d_out;
    float* out_grad = out + GRAD_OUT_OFFSET;

    prep_kernel<<<PREP_BLOCKS, 1024>>>(gstruct, gatom, values, sid, out);
    gather_kernel<<<GATHER_BLOCKS, 256>>>(grad4, out_grad);
}

// round 11
// speedup vs baseline: 1.0854x; 1.0015x over previous
#include <cuda_runtime.h>
#include <stdint.h>

#define N_STRUCT   1000
#define ATOMS      100
#define N_SAMP     100000
#define N_GRAD     500000
#define DFEAT      128
#define NSEG       (N_STRUCT * ATOMS)      // 100000
#define ROW_F4     96                      // 3*128/4
#define GRAD_OUT_OFFSET (N_STRUCT * DFEAT)

// prep: 148 worker blocks (1/SM), tile 680 segments each (148*680 >= 100000)
#define WORK_NB    148
#define TILE       680
#define PREP_THREADS (WORK_NB * 1024)          // 151552

#define VALUES_NB  ((N_STRUCT + 7) / 8)        // 125
#define PREP_BLOCKS (WORK_NB + VALUES_NB)      // 273 (all co-resident)

#define GATHER_BLOCKS (NSEG / 8)               // 12500 (8 warps/blk, 1 seg/warp)

// -------- scratch (device globals; zero-initialized at module load) --------
// Invariants at kernel_launch entry (restored by gather every call):
//   g_count == 0, g_bsum == 0, g_sync1 == 0, g_sync2 == 0
__device__ int g_count[NSEG];
__device__ int g_start[NSEG + 1];
__device__ int g_rows[N_GRAD];
__device__ int g_segpos[N_GRAD];   // (seg << 8) | within-segment rank
__device__ int g_bsum[WORK_NB];    // tile-sum + 1 (0 == not ready)
__device__ int g_sync1, g_sync2;   // grid-sync counters (worker blocks only)

// ---------------------------------------------------------------------------
// Kernel 1 (persistent prep):
//   bid <  WORK_NB : count -> gridsync -> scan(+lookback) -> gridsync -> scatter
//   bid >= WORK_NB : values segment-sums (no sync participation)
// ---------------------------------------------------------------------------
__global__ __launch_bounds__(1024) void prep_kernel(
        const int*   __restrict__ gstruct,
        const int*   __restrict__ gatom,
        const float* __restrict__ values,
        const int*   __restrict__ sid,
        float*       __restrict__ out) {
    if (blockIdx.x < WORK_NB) {
        int tid = threadIdx.x;
        int b   = blockIdx.x;
        int gth = b * 1024 + tid;

        // --- phase 1: degree count; atomicAdd return value = rank ---
        for (int r = gth; r < N_GRAD; r += PREP_THREADS) {
            int seg = __ldcs(gstruct + r) * ATOMS + __ldcs(gatom + r);
            int pos = atomicAdd(&g_count[seg], 1);
            g_segpos[r] = (seg << 8) | pos;          // pos <= ~25
        }
        __syncthreads();
        if (tid == 0) {
            __threadfence();
            atomicAdd(&g_sync1, 1);
            volatile int* p = &g_sync1;
            while (*p < WORK_NB) { }
        }
        __syncthreads();

        // --- phase 2: tile scan (680 segs/block) + decoupled lookback ---
        __shared__ int sh[1024];
        __shared__ int s_boff;
        int i = b * TILE + tid;                      // tid < TILE valid
        int v = (tid < TILE && i < NSEG) ? g_count[i] : 0;
        sh[tid] = v;
        __syncthreads();
        for (int off = 1; off < 1024; off <<= 1) {
            int t = (tid >= off) ? sh[tid - off] : 0;
            __syncthreads();
            sh[tid] += t;
            __syncthreads();
        }
        if (tid == 1023) {
            volatile int* p = g_bsum;
            p[b] = sh[1023] + 1;                     // tile total (+1 = ready)
        }
        if (tid < 32) {                               // lookback j < b
            int acc = 0;
            volatile int* p = g_bsum;
            for (int j = tid; j < b; j += 32) {
                int w;
                while ((w = p[j]) == 0) { }
                acc += w - 1;
            }
            #pragma unroll
            for (int off = 16; off > 0; off >>= 1)
                acc += __shfl_down_sync(0xffffffffu, acc, off);
            if (tid == 0) s_boff = acc;
        }
        __syncthreads();
        if (tid < TILE && i < NSEG) g_start[i] = sh[tid] - v + s_boff;
        if (i == NSEG - 1) g_start[NSEG] = N_GRAD;

        __syncthreads();
        if (tid == 0) {
            __threadfence();
            atomicAdd(&g_sync2, 1);
            volatile int* p = &g_sync2;
            while (*p < WORK_NB) { }
        }
        __syncthreads();

        // --- phase 3: atomic-free scatter ---
        for (int r = gth; r < N_GRAD; r += PREP_THREADS) {
            int sp  = g_segpos[r];
            int seg = sp >> 8;
            g_rows[g_start[seg] + (sp & 255)] = r;
        }
    } else {
        // --- values segment-sum: 8 structures per block (sorted -> bsearch)
        int vb  = blockIdx.x - WORK_NB;
        int sub = threadIdx.x >> 7;            // 0..7
        int d   = threadIdx.x & 127;
        int s   = vb * 8 + sub;

        __shared__ int s_lo[8], s_hi[8];
        if (s < N_STRUCT) {
            if (d == 0) {
                int lo = 0, hi = N_SAMP;
                while (lo < hi) { int m = (lo + hi) >> 1; if (sid[m] < s) lo = m + 1; else hi = m; }
                s_lo[sub] = lo;
                lo = s_lo[sub]; hi = N_SAMP;
                while (lo < hi) { int m = (lo + hi) >> 1; if (sid[m] < s + 1) lo = m + 1; else hi = m; }
                s_hi[sub] = lo;
            }
        }
        __syncthreads();
        if (s >= N_STRUCT) return;

        int lo = s_lo[sub], hi = s_hi[sub];
        float a0 = 0.f, a1 = 0.f, a2 = 0.f, a3 = 0.f;
        int r = lo;
        for (; r + 3 < hi; r += 4) {
            a0 += __ldcs(values + (long long)(r    ) * DFEAT + d);
            a1 += __ldcs(values + (long long)(r + 1) * DFEAT + d);
            a2 += __ldcs(values + (long long)(r + 2) * DFEAT + d);
            a3 += __ldcs(values + (long long)(r + 3) * DFEAT + d);
        }
        for (; r < hi; ++r)
            a0 += __ldcs(values + (long long)r * DFEAT + d);
        __stcs(out + (long long)s * DFEAT + d, (a0 + a1) + (a2 + a3));
    }
}

// ---------------------------------------------------------------------------
// Kernel 2: gather-reduce — EXACT R9 hot path (proven 146.2us @ 6.1+TB/s).
// One warp per segment; row ids prefetched into lanes + shfl broadcast ->
// all 3*cnt loads address-ready. Restores all scratch invariants.
// ---------------------------------------------------------------------------
__global__ void gather_kernel(const float4* __restrict__ grad4,
                              float*        __restrict__ out_grad) {
    int zi = blockIdx.x * 256 + threadIdx.x;
    if (zi < NSEG) g_count[zi] = 0;
    if (zi < WORK_NB) g_bsum[zi] = 0;
    if (zi == 0) { g_sync1 = 0; g_sync2 = 0; }

    int warp_id = (blockIdx.x * 256 + threadIdx.x) >> 5;
    int lane    = threadIdx.x & 31;

    int lo  = g_start[warp_id];
    int hi  = g_start[warp_id + 1];
    int cnt = hi - lo;

    int rid = (lane < cnt) ? g_rows[lo + lane] : 0;

    float4 a0 = make_float4(0.f, 0.f, 0.f, 0.f);
    float4 a1 = a0, a2 = a0;

    int n32 = cnt < 32 ? cnt : 32;
    #pragma unroll 4
    for (int p = 0; p < n32; ++p) {
        long long row = __shfl_sync(0xffffffffu, rid, p);
        const float4* src = grad4 + row * ROW_F4;
        float4 v0 = __ldcs(src + lane);
        float4 v1 = __ldcs(src + lane + 32);
        float4 v2 = __ldcs(src + lane + 64);
        a0.x += v0.x; a0.y += v0.y; a0.z += v0.z; a0.w += v0.w;
        a1.x += v1.x; a1.y += v1.y; a1.z += v1.z; a1.w += v1.w;
        a2.x += v2.x; a2.y += v2.y; a2.z += v2.z; a2.w += v2.w;
    }
    for (int p = 32; p < cnt; ++p) {         // overflow fallback (never hit)
        long long row = g_rows[lo + p];
        const float4* src = grad4 + row * ROW_F4;
        float4 v0 = __ldcs(src + lane);
        float4 v1 = __ldcs(src + lane + 32);
        float4 v2 = __ldcs(src + lane + 64);
        a0.x += v0.x; a0.y += v0.y; a0.z += v0.z; a0.w += v0.w;
        a1.x += v1.x; a1.y += v1.y; a1.z += v1.z; a1.w += v1.w;
        a2.x += v2.x; a2.y += v2.y; a2.z += v2.z; a2.w += v2.w;
    }

    float4* dst = (float4*)(out_grad + (long long)warp_id * (3 * DFEAT));
    __stcs(dst + lane,      a0);
    __stcs(dst + lane + 32, a1);
    __stcs(dst + lane + 64, a2);
}

// ---------------------------------------------------------------------------
extern "C" void kernel_launch(void* const* d_in, const int* in_sizes, int n_in,
                              void* d_out, int out_size) {
    const float*  values  = (const float*)d_in[0];
    const int*    sid     = (const int*)  d_in[1];
    const float4* grad4   = (const float4*)d_in[2];
    const int*    gstruct = (const int*)  d_in[3];
    const int*    gatom   = (const int*)  d_in[4];

    float* out      = (float*)d_out;
    float* out_grad = out + GRAD_OUT_OFFSET;

    prep_kernel<<<PREP_BLOCKS, 1024>>>(gstruct, gatom, values, sid, out);
    gather_kernel<<<GATHER_BLOCKS, 256>>>(grad4, out_grad);
}